// round 11
// baseline (speedup 1.0000x reference)
#include <cuda_runtime.h>
#include <cuda_bf16.h>
#include <stdint.h>
#include <math.h>

#define BB 128
#define LC 256
#define LE 1024
#define DD 256
#define MM 512
#define NEGV (-1e9f)
#define SAW 40   // smem row stride in bf16 (80B, pad 8)

// ---------------- scratch (byte offsets, aliased) ----------------
#define SZ_CLD  ((size_t)BB * LC * DD * 2)
#define SZ_LED  ((size_t)BB * LE * DD * 2)
#define O_CB    ((size_t)0)                          // c bf16 -> attc
#define O_EB    (O_CB + SZ_CLD)                      // e bf16 -> betaT
#define O_ALIGN (O_EB + SZ_LED)                      // align f32
#define O_ALPHA (O_ALIGN + (size_t)BB * LC * LE * 4) // alpha bf16 -> atte
#define O_EHRT  (O_ALPHA + SZ_LED)
#define O_CRITT (O_EHRT + SZ_LED)
#define O_WAT   (O_CRITT + SZ_CLD)
#define O_WRT   (O_WAT + (size_t)DD * DD * 2)
#define O_R1    (O_WRT + (size_t)2 * DD * DD * 2)
#define O_R2    (O_R1 + (size_t)BB * DD * 4)
#define SCRATCH_BYTES (O_R2 + (size_t)BB * DD * 4)
__device__ char g_scratch[SCRATCH_BYTES];

// ---------------- helpers ----------------
__device__ __forceinline__ uint32_t smem_u32(const void* p) {
    uint32_t a;
    asm("{ .reg .u64 t; cvta.to.shared.u64 t, %1; cvt.u32.u64 %0, t; }" : "=r"(a) : "l"(p));
    return a;
}
__device__ __forceinline__ uint32_t pk(float lo, float hi) {
    __nv_bfloat162 h = __floats2bfloat162_rn(lo, hi);
    return *reinterpret_cast<uint32_t*>(&h);
}
__device__ __forceinline__ void ldsm4(uint32_t* d, uint32_t a) {
    asm volatile("ldmatrix.sync.aligned.m8n8.x4.shared.b16 {%0,%1,%2,%3}, [%4];"
        : "=r"(d[0]), "=r"(d[1]), "=r"(d[2]), "=r"(d[3]) : "r"(a));
}
__device__ __forceinline__ void mma_bf16(float* c, const uint32_t* a, const uint32_t* b) {
    asm volatile(
        "mma.sync.aligned.m16n8k16.row.col.f32.bf16.bf16.f32 "
        "{%0,%1,%2,%3}, {%4,%5,%6,%7}, {%8,%9}, {%0,%1,%2,%3};"
        : "+f"(c[0]), "+f"(c[1]), "+f"(c[2]), "+f"(c[3])
        : "r"(a[0]), "r"(a[1]), "r"(a[2]), "r"(a[3]), "r"(b[0]), "r"(b[1]));
}

enum { A_F32 = 0, A_BF16 = 1, A_CONCAT = 2 };
enum { E_F32 = 0, E_BF16 = 1, E_BIASRELU = 2, E_COLSUM = 3 };

// Uniform NT GEMM: C(M,Ntot) = A(M,K) @ B(Ntot,K)^T. bf16 mma + ldmatrix.
// BM=BN=128, BK=32, 256 thr, 8 warps @ 64x32 (wm=(wid&1)*64, wn=(wid>>1)*32).
template <int ASRC, int EPI>
__global__ __launch_bounds__(256, 2) void mm_nt(
    const void* __restrict__ Ap, const float* __restrict__ A2p,
    const __nv_bfloat16* __restrict__ Bp, const float* __restrict__ bias,
    void* __restrict__ Cp, int Ntot, int K, int lda,
    size_t sA, size_t sA2, size_t sB, size_t sC)
{
    __shared__ __align__(16) __nv_bfloat16 Asm[128 * SAW];
    __shared__ __align__(16) __nv_bfloat16 Bsm[128 * SAW];
    __shared__ float colsum[128];
    const int tid = threadIdx.x, lane = tid & 31, wid = tid >> 5;
    const int wm = (wid & 1) * 64, wn = (wid >> 1) * 32;
    const int m0 = blockIdx.y * 128, n0 = blockIdx.x * 128, z = blockIdx.z;
    if (EPI == E_COLSUM && tid < 128) colsum[tid] = 0.f;

    const __nv_bfloat16* Ab = (const __nv_bfloat16*)Ap + (size_t)z * sA;
    const float* Af = (const float*)Ap + (size_t)z * sA;
    const float* A2 = (ASRC == A_CONCAT) ? A2p + (size_t)z * sA2 : nullptr;
    const __nv_bfloat16* Bb = Bp + (size_t)z * sB;

    // chunk mapping: thread covers rows r0c and r0c+64, 8 k-elems at posk
    const int r0c = tid >> 2, posk = (tid & 3) * 8;

    uint4 ra[2], rb[2];
    float4 rf[4];
    auto loadA = [&](int k0) {
        if (ASRC == A_BF16) {
            ra[0] = *(const uint4*)(Ab + (size_t)(m0 + r0c) * lda + k0 + posk);
            ra[1] = *(const uint4*)(Ab + (size_t)(m0 + r0c + 64) * lda + k0 + posk);
        } else if (ASRC == A_F32) {
            const float* s0 = Af + (size_t)(m0 + r0c) * lda + k0 + posk;
            const float* s1 = Af + (size_t)(m0 + r0c + 64) * lda + k0 + posk;
            rf[0] = *(const float4*)s0; rf[1] = *(const float4*)(s0 + 4);
            rf[2] = *(const float4*)s1; rf[3] = *(const float4*)(s1 + 4);
        } else {
            if (k0 < DD) {
                ra[0] = *(const uint4*)(Ab + (size_t)(m0 + r0c) * DD + k0 + posk);
                ra[1] = *(const uint4*)(Ab + (size_t)(m0 + r0c + 64) * DD + k0 + posk);
            } else {
                const float* s0 = A2 + (size_t)(m0 + r0c) * DD + (k0 - DD) + posk;
                const float* s1 = A2 + (size_t)(m0 + r0c + 64) * DD + (k0 - DD) + posk;
                rf[0] = *(const float4*)s0; rf[1] = *(const float4*)(s0 + 4);
                rf[2] = *(const float4*)s1; rf[3] = *(const float4*)(s1 + 4);
            }
        }
        rb[0] = *(const uint4*)(Bb + (size_t)(n0 + r0c) * K + k0 + posk);
        rb[1] = *(const uint4*)(Bb + (size_t)(n0 + r0c + 64) * K + k0 + posk);
    };
    auto stsAll = [&](bool f32src) {
        __nv_bfloat16* d0 = Asm + r0c * SAW + posk;
        __nv_bfloat16* d1 = Asm + (r0c + 64) * SAW + posk;
        if (!f32src) { *(uint4*)d0 = ra[0]; *(uint4*)d1 = ra[1]; }
        else {
            *(uint4*)d0 = make_uint4(pk(rf[0].x, rf[0].y), pk(rf[0].z, rf[0].w),
                                     pk(rf[1].x, rf[1].y), pk(rf[1].z, rf[1].w));
            *(uint4*)d1 = make_uint4(pk(rf[2].x, rf[2].y), pk(rf[2].z, rf[2].w),
                                     pk(rf[3].x, rf[3].y), pk(rf[3].z, rf[3].w));
        }
        *(uint4*)(Bsm + r0c * SAW + posk) = rb[0];
        *(uint4*)(Bsm + (r0c + 64) * SAW + posk) = rb[1];
    };

    // ldmatrix lane addresses (x4: matrices from lane groups of 8)
    const uint32_t ab = smem_u32(Asm), bb = smem_u32(Bsm);
    const int lr = lane & 7, lh = lane >> 3;
    uint32_t aAddr[4], bAddr[2];
#pragma unroll
    for (int mi = 0; mi < 4; mi++)   // a0:(r0-7,k0-7) a1:(r8-15,k0-7) a2:(r0-7,k8-15) a3:(r8-15,k8-15)
        aAddr[mi] = ab + (uint32_t)((wm + mi * 16 + (lh & 1) * 8 + lr) * (SAW * 2) + (lh >> 1) * 16);
#pragma unroll
    for (int p = 0; p < 2; p++)      // d0:b0(ni=2p) d1:b1(ni=2p) d2:b0(ni=2p+1) d3:b1(ni=2p+1)
        bAddr[p] = bb + (uint32_t)((wn + p * 16 + (lh >> 1) * 8 + lr) * (SAW * 2) + (lh & 1) * 16);

    float acc[4][4][4] = {};
    const int nT = K / 32;
    loadA(0);
    for (int t = 0; t < nT; t++) {
        stsAll(ASRC == A_F32 || (ASRC == A_CONCAT && t * 32 >= DD));
        __syncthreads();
        if (t + 1 < nT) loadA((t + 1) * 32);
#pragma unroll
        for (int s = 0; s < 2; s++) {
            uint32_t af[4][4], bf[4][2], bt[4];
#pragma unroll
            for (int mi = 0; mi < 4; mi++) ldsm4(af[mi], aAddr[mi] + s * 32);
#pragma unroll
            for (int p = 0; p < 2; p++) {
                ldsm4(bt, bAddr[p] + s * 32);
                bf[2 * p][0] = bt[0]; bf[2 * p][1] = bt[1];
                bf[2 * p + 1][0] = bt[2]; bf[2 * p + 1][1] = bt[3];
            }
#pragma unroll
            for (int mi = 0; mi < 4; mi++)
#pragma unroll
                for (int ni = 0; ni < 4; ni++) mma_bf16(acc[mi][ni], af[mi], bf[ni]);
        }
        __syncthreads();
    }

    const int c4 = lane & 3, g8 = lane >> 2;
    if (EPI == E_COLSUM) {
#pragma unroll
        for (int ni = 0; ni < 4; ni++) {
            int col = wn + ni * 8 + 2 * c4;
            float b0 = bias[n0 + col], b1 = bias[n0 + col + 1];
            float s0 = 0.f, s1 = 0.f;
#pragma unroll
            for (int mi = 0; mi < 4; mi++) {
                s0 += fmaxf(acc[mi][ni][0] + b0, 0.f) + fmaxf(acc[mi][ni][2] + b0, 0.f);
                s1 += fmaxf(acc[mi][ni][1] + b1, 0.f) + fmaxf(acc[mi][ni][3] + b1, 0.f);
            }
            atomicAdd(&colsum[col], s0);
            atomicAdd(&colsum[col + 1], s1);
        }
        __syncthreads();
        if (tid < 128) atomicAdd((float*)Cp + (size_t)z * sC + n0 + tid, colsum[tid]);
        return;
    }
#pragma unroll
    for (int mi = 0; mi < 4; mi++)
#pragma unroll
        for (int ni = 0; ni < 4; ni++) {
            int row = m0 + wm + mi * 16 + g8;
            int col = n0 + wn + ni * 8 + 2 * c4;
            float v0 = acc[mi][ni][0], v1 = acc[mi][ni][1];
            float v2 = acc[mi][ni][2], v3 = acc[mi][ni][3];
            if (EPI == E_BIASRELU) {
                float b0 = bias[col], b1 = bias[col + 1];
                v0 = fmaxf(v0 + b0, 0.f); v1 = fmaxf(v1 + b1, 0.f);
                v2 = fmaxf(v2 + b0, 0.f); v3 = fmaxf(v3 + b1, 0.f);
            }
            if (EPI == E_F32) {
                float* C = (float*)Cp + (size_t)z * sC;
                *(float2*)&C[(size_t)row * Ntot + col] = make_float2(v0, v1);
                *(float2*)&C[(size_t)(row + 8) * Ntot + col] = make_float2(v2, v3);
            } else {
                __nv_bfloat16* C = (__nv_bfloat16*)Cp + (size_t)z * sC;
                *(uint32_t*)&C[(size_t)row * Ntot + col] = pk(v0, v1);
                *(uint32_t*)&C[(size_t)(row + 8) * Ntot + col] = pk(v2, v3);
            }
        }
}

// Batched transpose f32 -> bf16: out[c][r] = in[r][c]. grid (C/32, R/32, batch), block (32,8)
__global__ void tr_kernel(const float* __restrict__ in, __nv_bfloat16* __restrict__ out,
                          int R, int C, size_t sIn, size_t sOut)
{
    __shared__ float t[32][33];
    const int z = blockIdx.z;
    in += (size_t)z * sIn; out += (size_t)z * sOut;
    const int r0 = blockIdx.y * 32, c0 = blockIdx.x * 32;
    const int tx = threadIdx.x, ty = threadIdx.y;
#pragma unroll
    for (int j = 0; j < 4; j++)
        t[ty + j * 8][tx] = in[(size_t)(r0 + ty + j * 8) * C + c0 + tx];
    __syncthreads();
#pragma unroll
    for (int j = 0; j < 4; j++)
        out[(size_t)(c0 + ty + j * 8) * R + r0 + tx] = __float2bfloat16_rn(t[tx][ty + j * 8]);
}

// betaT_bf16[e][l] = softmax over Lc of align (masked). grid (LE/32, B), block (32,8)
__global__ void beta_kernel(const float* __restrict__ align_, __nv_bfloat16* __restrict__ betaT,
                            const int* __restrict__ cmask)
{
    const int b = blockIdx.y, e0 = blockIdx.x * 32;
    const int tx = threadIdx.x, ty = threadIdx.y, tid = ty * 32 + tx;
    const float* base = align_ + (size_t)b * LC * LE + e0 + tx;
    __shared__ float red[8][32];
    __shared__ uint16_t tbuf[32][258];

    float vals[LC / 8];
    float mx = -INFINITY;
#pragma unroll
    for (int i = 0; i < LC / 8; i++) {
        int l = ty + i * 8;
        float v = base[(size_t)l * LE] + (1.0f - (float)cmask[b * LC + l]) * NEGV;
        vals[i] = v;
        mx = fmaxf(mx, v);
    }
    red[ty][tx] = mx;
    __syncthreads();
    if (ty == 0) {
        float m2 = red[0][tx];
#pragma unroll
        for (int i = 1; i < 8; i++) m2 = fmaxf(m2, red[i][tx]);
        red[0][tx] = m2;
    }
    __syncthreads();
    mx = red[0][tx];
    __syncthreads();
    float s = 0.0f;
#pragma unroll
    for (int i = 0; i < LC / 8; i++) { vals[i] = expf(vals[i] - mx); s += vals[i]; }
    red[ty][tx] = s;
    __syncthreads();
    if (ty == 0) {
        float s2 = 0.0f;
#pragma unroll
        for (int i = 0; i < 8; i++) s2 += red[i][tx];
        red[0][tx] = s2;
    }
    __syncthreads();
    float inv = 1.0f / red[0][tx];
#pragma unroll
    for (int i = 0; i < LC / 8; i++) {
        __nv_bfloat16 h = __float2bfloat16_rn(vals[i] * inv);
        tbuf[tx][ty + i * 8] = *reinterpret_cast<uint16_t*>(&h);
    }
    __syncthreads();
    int er = tid >> 3, lc = (tid & 7) * 32;
    __nv_bfloat16* o = betaT + ((size_t)b * LE + e0 + er) * LC + lc;
#pragma unroll
    for (int c = 0; c < 32; c++)
        *reinterpret_cast<uint16_t*>(o + c) = tbuf[er][lc + c];
}

// alpha_bf16 = softmax over Le (rows of align), masked. grid (LC, B), block 256
__global__ void alpha_kernel(const float* __restrict__ align_, __nv_bfloat16* __restrict__ alpha,
                             const int* __restrict__ emask)
{
    const int b = blockIdx.y, l = blockIdx.x, t = threadIdx.x;
    const float* row = align_ + ((size_t)b * LC + l) * LE;
    __nv_bfloat16* arow = alpha + ((size_t)b * LC + l) * LE;
    float v[4];
    float mx = -INFINITY;
#pragma unroll
    for (int j = 0; j < 4; j++) {
        int e = t + j * 256;
        v[j] = row[e] + (1.0f - (float)emask[b * LE + e]) * NEGV;
        mx = fmaxf(mx, v[j]);
    }
    __shared__ float sm[256];
    sm[t] = mx;
    __syncthreads();
    for (int s = 128; s > 0; s >>= 1) { if (t < s) sm[t] = fmaxf(sm[t], sm[t + s]); __syncthreads(); }
    mx = sm[0];
    __syncthreads();
    float sum = 0.0f;
#pragma unroll
    for (int j = 0; j < 4; j++) { v[j] = expf(v[j] - mx); sum += v[j]; }
    sm[t] = sum;
    __syncthreads();
    for (int s = 128; s > 0; s >>= 1) { if (t < s) sm[t] += sm[t + s]; __syncthreads(); }
    float inv = 1.0f / sm[0];
#pragma unroll
    for (int j = 0; j < 4; j++) arow[t + j * 256] = __float2bfloat16_rn(v[j] * inv);
}

__global__ void head_kernel(const float* __restrict__ r1, const float* __restrict__ r2,
                            const float* __restrict__ Wm, const float* __restrict__ bm,
                            const float* __restrict__ Wo, const float* __restrict__ bo,
                            float* __restrict__ out)
{
    const int b = blockIdx.x, t = threadIdx.x;
    __shared__ float mv[4 * DD];
    __shared__ float outacc[3];
    if (t < DD) {
        float a = r1[(size_t)b * DD + t], c = r2[(size_t)b * DD + t];
        mv[t] = a; mv[DD + t] = c; mv[2 * DD + t] = a * c; mv[3 * DD + t] = a - c;
    }
    if (t < 3) outacc[t] = 0.0f;
    __syncthreads();
    float acc = bm[t];
#pragma unroll 8
    for (int k = 0; k < 4 * DD; k++) acc = fmaf(mv[k], Wm[(size_t)k * MM + t], acc);
    float h = fmaxf(acc, 0.0f);
#pragma unroll
    for (int i = 0; i < 3; i++) atomicAdd(&outacc[i], h * Wo[(size_t)t * 3 + i]);
    __syncthreads();
    if (t < 3) out[(size_t)b * 3 + t] = outacc[t] + bo[t];
}

// ---------------- launch ----------------
extern "C" void kernel_launch(void* const* d_in, const int* in_sizes, int n_in,
                              void* d_out, int out_size)
{
    const float* criteria = (const float*)d_in[0];
    const float* ehr      = (const float*)d_in[1];
    const int*   cmask    = (const int*)d_in[2];
    const int*   emask    = (const int*)d_in[3];
    const float* Wa       = (const float*)d_in[4];
    const float* ba       = (const float*)d_in[5];
    const float* Wr       = (const float*)d_in[6];
    const float* br       = (const float*)d_in[7];
    const float* Wm       = (const float*)d_in[8];
    const float* bm       = (const float*)d_in[9];
    const float* Wo       = (const float*)d_in[10];
    const float* bo       = (const float*)d_in[11];
    float* out = (float*)d_out;

    char* base;
    cudaGetSymbolAddress((void**)&base, g_scratch);
    __nv_bfloat16* p_c     = (__nv_bfloat16*)(base + O_CB);
    __nv_bfloat16* p_e     = (__nv_bfloat16*)(base + O_EB);
    float*         p_align = (float*)(base + O_ALIGN);
    __nv_bfloat16* p_betaT = (__nv_bfloat16*)(base + O_EB);     // alias: e dead after align
    __nv_bfloat16* p_alpha = (__nv_bfloat16*)(base + O_ALPHA);
    __nv_bfloat16* p_attc  = (__nv_bfloat16*)(base + O_CB);     // alias: c dead after align
    __nv_bfloat16* p_atte  = (__nv_bfloat16*)(base + O_ALPHA);  // alias: alpha dead after attc
    __nv_bfloat16* p_ehrT  = (__nv_bfloat16*)(base + O_EHRT);
    __nv_bfloat16* p_critT = (__nv_bfloat16*)(base + O_CRITT);
    __nv_bfloat16* p_WaT   = (__nv_bfloat16*)(base + O_WAT);
    __nv_bfloat16* p_WrT   = (__nv_bfloat16*)(base + O_WRT);
    float*         p_r1    = (float*)(base + O_R1);
    float*         p_r2    = (float*)(base + O_R2);

    dim3 b328(32, 8);
    // 0) transposes -> bf16 (_rn: same quantization as R7)
    tr_kernel<<<dim3(DD / 32, DD / 32, 1), b328>>>(Wa, p_WaT, DD, DD, 0, 0);
    tr_kernel<<<dim3(DD / 32, (2 * DD) / 32, 1), b328>>>(Wr, p_WrT, 2 * DD, DD, 0, 0);
    tr_kernel<<<dim3(DD / 32, LE / 32, BB), b328>>>(ehr, p_ehrT, LE, DD,
        (size_t)LE * DD, (size_t)DD * LE);
    tr_kernel<<<dim3(DD / 32, LC / 32, BB), b328>>>(criteria, p_critT, LC, DD,
        (size_t)LC * DD, (size_t)DD * LC);
    // 1) c = relu(criteria @ WaT^T + ba) -> bf16
    mm_nt<A_F32, E_BIASRELU><<<dim3(2, (BB * LC) / 128, 1), 256>>>(
        criteria, nullptr, p_WaT, ba, p_c, DD, DD, DD, 0, 0, 0, 0);
    // 2) e = relu(ehr @ WaT^T + ba) -> bf16
    mm_nt<A_F32, E_BIASRELU><<<dim3(2, (BB * LE) / 128, 1), 256>>>(
        ehr, nullptr, p_WaT, ba, p_e, DD, DD, DD, 0, 0, 0, 0);
    // 3) align = c @ e^T -> f32
    mm_nt<A_BF16, E_F32><<<dim3(LE / 128, LC / 128, BB), 256>>>(
        p_c, nullptr, p_e, nullptr, p_align, LE, DD, DD,
        (size_t)LC * DD, 0, (size_t)LE * DD, (size_t)LC * LE);
    // 4) betaT (softmax over Lc, transposed out) -> bf16, aliases e
    beta_kernel<<<dim3(LE / 32, BB), b328>>>(p_align, p_betaT, cmask);
    // 5) alpha (softmax over Le) -> bf16
    alpha_kernel<<<dim3(LC, BB), 256>>>(p_align, p_alpha, emask);
    // 6) attc = alpha @ ehrT^T -> bf16, aliases c
    mm_nt<A_BF16, E_BF16><<<dim3(DD / 128, LC / 128, BB), 256>>>(
        p_alpha, nullptr, p_ehrT, nullptr, p_attc, DD, LE, LE,
        (size_t)LC * LE, 0, (size_t)DD * LE, (size_t)LC * DD);
    // 7) atte = betaT @ critT^T -> bf16, aliases alpha
    mm_nt<A_BF16, E_BF16><<<dim3(DD / 128, LE / 128, BB), 256>>>(
        p_betaT, nullptr, p_critT, nullptr, p_atte, DD, LC, LC,
        (size_t)LE * LC, 0, (size_t)DD * LC, (size_t)LE * DD);
    // 8) r1, r2: concat GEMM vs WrT + relu + col-sum
    cudaMemsetAsync(p_r1, 0, (size_t)2 * BB * DD * sizeof(float));
    mm_nt<A_CONCAT, E_COLSUM><<<dim3(DD / 128, LC / 128, BB), 256>>>(
        p_attc, criteria, p_WrT, br, p_r1, DD, 2 * DD, DD,
        (size_t)LC * DD, (size_t)LC * DD, 0, DD);
    mm_nt<A_CONCAT, E_COLSUM><<<dim3(DD / 128, LE / 128, BB), 256>>>(
        p_atte, ehr, p_WrT, br, p_r2, DD, 2 * DD, DD,
        (size_t)LE * DD, (size_t)LE * DD, 0, DD);
    // 9) head
    head_kernel<<<BB, MM>>>(p_r1, p_r2, Wm, bm, Wo, bo, out);
}

// round 12
// speedup vs baseline: 1.0751x; 1.0751x over previous
#include <cuda_runtime.h>
#include <cuda_bf16.h>
#include <math.h>
#include <stdint.h>

#define BB 128
#define LC 256
#define LE 1024
#define DD 256
#define MM 512
#define NEGV (-1e9f)

#define BM 128
#define BN 128
#define BKE 32
#define PA 132
#define PB 132

// ---------------- scratch (aliased; float units) ----------------
#define HCLD ((size_t)BB * LC * DD / 2)
#define HLED ((size_t)BB * LE * DD / 2)
#define HLCE ((size_t)BB * LC * LE / 2)
#define OFF_CB    ((size_t)0)
#define OFF_EB    (OFF_CB + HCLD)
#define OFF_ALIGN (OFF_EB + HLED)
#define OFF_ALPHA (OFF_ALIGN + (size_t)BB * LC * LE)
#define OFF_ATTE  (OFF_ALPHA + HLCE)
#define OFF_R1    (OFF_ATTE + HLED)
#define OFF_R2    (OFF_R1 + (size_t)BB * DD)
#define SCRATCH_FLOATS (OFF_R2 + (size_t)BB * DD)
__device__ float g_scratch[SCRATCH_FLOATS];

// ---------------- helpers (identical to R7) ----------------
__device__ __forceinline__ uint32_t pk(float lo, float hi) {
    __nv_bfloat162 h = __floats2bfloat162_rn(lo, hi);
    return *reinterpret_cast<uint32_t*>(&h);
}
__device__ __forceinline__ uint4 pk4(float4 a, float4 b) {
    return make_uint4(pk(a.x, b.x), pk(a.y, b.y), pk(a.z, b.z), pk(a.w, b.w));
}
__device__ __forceinline__ uint32_t prmt(uint32_t a, uint32_t b, uint32_t c) {
    uint32_t d;
    asm("prmt.b32 %0, %1, %2, %3;" : "=r"(d) : "r"(a), "r"(b), "r"(c));
    return d;
}
__device__ __forceinline__ void mma_bf16(float* c, const uint32_t* a, const uint32_t* b) {
    asm volatile(
        "mma.sync.aligned.m16n8k16.row.col.f32.bf16.bf16.f32 "
        "{%0,%1,%2,%3}, {%4,%5,%6,%7}, {%8,%9}, {%0,%1,%2,%3};"
        : "+f"(c[0]), "+f"(c[1]), "+f"(c[2]), "+f"(c[3])
        : "r"(a[0]), "r"(a[1]), "r"(a[2]), "r"(a[3]), "r"(b[0]), "r"(b[1]));
}
__device__ __forceinline__ void mma_compute(
    const uint32_t (*As)[PA], const uint32_t (*Bs)[PB],
    int lane, int wm, int wn, float acc[4][4][4])
{
    const int c4 = lane & 3;
    const int g8 = lane >> 2;
#pragma unroll
    for (int ks = 0; ks < 16; ks += 8) {
        uint32_t af[4][4];
#pragma unroll
        for (int mi = 0; mi < 4; mi++) {
            int mrow = wm + mi * 16 + g8;
            af[mi][0] = As[ks + c4][mrow];
            af[mi][1] = As[ks + c4][mrow + 8];
            af[mi][2] = As[ks + c4 + 4][mrow];
            af[mi][3] = As[ks + c4 + 4][mrow + 8];
        }
        uint32_t bf[4][2];
#pragma unroll
        for (int ni = 0; ni < 4; ni++) {
            int ncol = wn + ni * 8 + g8;
            bf[ni][0] = Bs[ks + c4][ncol];
            bf[ni][1] = Bs[ks + c4 + 4][ncol];
        }
#pragma unroll
        for (int mi = 0; mi < 4; mi++)
#pragma unroll
            for (int ni = 0; ni < 4; ni++)
                mma_bf16(acc[mi][ni], af[mi], bf[ni]);
    }
}

// ---------------- GEMM kernels (R7 forms + double-buffered smem) ----------------

// Steps 1,2: C_bf16 = relu(A_f32 @ B_f32 + bias).
__global__ __launch_bounds__(256) void mm_proj(
    const float* __restrict__ A, const float* __restrict__ B,
    const float* __restrict__ bias, __nv_bfloat16* __restrict__ C, int N, int K)
{
    __shared__ uint32_t As[2][16][PA];
    __shared__ uint32_t Bs[2][16][PB];
    const int tid = threadIdx.x;
    const int lane = tid & 31, wid = tid >> 5;
    const int wm = (wid & 1) * 64, wn = (wid >> 1) * 32;
    const int m0 = blockIdx.y * BM, n0 = blockIdx.x * BN;
    const int aM = tid >> 2, aK = (tid & 3) * 8, aW = (tid & 3) * 4;
    const int bN4 = (tid & 31) * 4, bP = tid >> 5;

    float4 ra[4], rb[4];
    auto ld = [&](int k0) {
        ra[0] = *(const float4*)&A[(size_t)(m0 + aM) * K + k0 + aK];
        ra[1] = *(const float4*)&A[(size_t)(m0 + aM) * K + k0 + aK + 4];
        ra[2] = *(const float4*)&A[(size_t)(m0 + aM + 64) * K + k0 + aK];
        ra[3] = *(const float4*)&A[(size_t)(m0 + aM + 64) * K + k0 + aK + 4];
        rb[0] = *(const float4*)&B[(size_t)(k0 + 2 * bP) * N + n0 + bN4];
        rb[1] = *(const float4*)&B[(size_t)(k0 + 2 * bP + 1) * N + n0 + bN4];
        rb[2] = *(const float4*)&B[(size_t)(k0 + 2 * bP + 16) * N + n0 + bN4];
        rb[3] = *(const float4*)&B[(size_t)(k0 + 2 * bP + 17) * N + n0 + bN4];
    };
    auto sts = [&](int bf) {
        uint32_t (*A_)[PA] = As[bf];
        uint32_t (*B_)[PB] = Bs[bf];
        A_[aW + 0][aM] = pk(ra[0].x, ra[0].y);
        A_[aW + 1][aM] = pk(ra[0].z, ra[0].w);
        A_[aW + 2][aM] = pk(ra[1].x, ra[1].y);
        A_[aW + 3][aM] = pk(ra[1].z, ra[1].w);
        A_[aW + 0][aM + 64] = pk(ra[2].x, ra[2].y);
        A_[aW + 1][aM + 64] = pk(ra[2].z, ra[2].w);
        A_[aW + 2][aM + 64] = pk(ra[3].x, ra[3].y);
        A_[aW + 3][aM + 64] = pk(ra[3].z, ra[3].w);
        *(uint4*)&B_[bP][bN4] = pk4(rb[0], rb[1]);
        *(uint4*)&B_[bP + 8][bN4] = pk4(rb[2], rb[3]);
    };

    float acc[4][4][4] = {};
    const int nIters = K / BKE;
    ld(0);
    sts(0);
    __syncthreads();
    for (int it = 0; it < nIters; it++) {
        if (it + 1 < nIters) ld((it + 1) * BKE);
        mma_compute(As[it & 1], Bs[it & 1], lane, wm, wn, acc);
        if (it + 1 < nIters) sts((it + 1) & 1);
        __syncthreads();
    }
    const int c4 = lane & 3, g8 = lane >> 2;
#pragma unroll
    for (int mi = 0; mi < 4; mi++)
#pragma unroll
        for (int ni = 0; ni < 4; ni++) {
            int row = m0 + wm + mi * 16 + g8;
            int col = n0 + wn + ni * 8 + 2 * c4;
            float b0 = bias[col], b1 = bias[col + 1];
            *(uint32_t*)&C[(size_t)row * N + col] =
                pk(fmaxf(acc[mi][ni][0] + b0, 0.f), fmaxf(acc[mi][ni][1] + b1, 0.f));
            *(uint32_t*)&C[(size_t)(row + 8) * N + col] =
                pk(fmaxf(acc[mi][ni][2] + b0, 0.f), fmaxf(acc[mi][ni][3] + b1, 0.f));
        }
}

// Step 3: align_f32 = c_bf16 @ e_bf16^T (NT, batched).
__global__ __launch_bounds__(256) void mm_align(
    const __nv_bfloat16* __restrict__ A, const __nv_bfloat16* __restrict__ Bm,
    float* __restrict__ C, int N, int K, size_t sA, size_t sB, size_t sC)
{
    __shared__ uint32_t As[2][16][PA];
    __shared__ uint32_t Bs[2][16][PB];
    const int tid = threadIdx.x;
    const int lane = tid & 31, wid = tid >> 5;
    const int wm = (wid & 1) * 64, wn = (wid >> 1) * 32;
    const int m0 = blockIdx.y * BM, n0 = blockIdx.x * BN;
    A += (size_t)blockIdx.z * sA;
    Bm += (size_t)blockIdx.z * sB;
    C += (size_t)blockIdx.z * sC;
    const int aM = tid >> 2, aK = (tid & 3) * 8, aW = (tid & 3) * 4;

    uint4 qa[2], qb[2];
    auto ld = [&](int k0) {
        qa[0] = *(const uint4*)(A + (size_t)(m0 + aM) * K + k0 + aK);
        qa[1] = *(const uint4*)(A + (size_t)(m0 + aM + 64) * K + k0 + aK);
        qb[0] = *(const uint4*)(Bm + (size_t)(n0 + aM) * K + k0 + aK);
        qb[1] = *(const uint4*)(Bm + (size_t)(n0 + aM + 64) * K + k0 + aK);
    };
    auto sts = [&](int bf) {
        uint32_t (*A_)[PA] = As[bf];
        uint32_t (*B_)[PB] = Bs[bf];
        A_[aW + 0][aM] = qa[0].x; A_[aW + 1][aM] = qa[0].y;
        A_[aW + 2][aM] = qa[0].z; A_[aW + 3][aM] = qa[0].w;
        A_[aW + 0][aM + 64] = qa[1].x; A_[aW + 1][aM + 64] = qa[1].y;
        A_[aW + 2][aM + 64] = qa[1].z; A_[aW + 3][aM + 64] = qa[1].w;
        B_[aW + 0][aM] = qb[0].x; B_[aW + 1][aM] = qb[0].y;
        B_[aW + 2][aM] = qb[0].z; B_[aW + 3][aM] = qb[0].w;
        B_[aW + 0][aM + 64] = qb[1].x; B_[aW + 1][aM + 64] = qb[1].y;
        B_[aW + 2][aM + 64] = qb[1].z; B_[aW + 3][aM + 64] = qb[1].w;
    };

    float acc[4][4][4] = {};
    const int nIters = K / BKE;
    ld(0);
    sts(0);
    __syncthreads();
    for (int it = 0; it < nIters; it++) {
        if (it + 1 < nIters) ld((it + 1) * BKE);
        mma_compute(As[it & 1], Bs[it & 1], lane, wm, wn, acc);
        if (it + 1 < nIters) sts((it + 1) & 1);
        __syncthreads();
    }
    const int c4 = lane & 3, g8 = lane >> 2;
#pragma unroll
    for (int mi = 0; mi < 4; mi++)
#pragma unroll
        for (int ni = 0; ni < 4; ni++) {
            int row = m0 + wm + mi * 16 + g8;
            int col = n0 + wn + ni * 8 + 2 * c4;
            *(float2*)&C[(size_t)row * N + col] = make_float2(acc[mi][ni][0], acc[mi][ni][1]);
            *(float2*)&C[(size_t)(row + 8) * N + col] = make_float2(acc[mi][ni][2], acc[mi][ni][3]);
        }
}

// Step 6: attc_bf16 = alpha_bf16 @ ehr_f32 (NN, batched).
__global__ __launch_bounds__(256) void mm_attc(
    const __nv_bfloat16* __restrict__ A, const float* __restrict__ B,
    __nv_bfloat16* __restrict__ C, int N, int K, size_t sA, size_t sB, size_t sC)
{
    __shared__ uint32_t As[2][16][PA];
    __shared__ uint32_t Bs[2][16][PB];
    const int tid = threadIdx.x;
    const int lane = tid & 31, wid = tid >> 5;
    const int wm = (wid & 1) * 64, wn = (wid >> 1) * 32;
    const int m0 = blockIdx.y * BM, n0 = blockIdx.x * BN;
    A += (size_t)blockIdx.z * sA;
    B += (size_t)blockIdx.z * sB;
    C += (size_t)blockIdx.z * sC;
    const int aM = tid >> 2, aK = (tid & 3) * 8, aW = (tid & 3) * 4;
    const int bN4 = (tid & 31) * 4, bP = tid >> 5;

    uint4 qa[2];
    float4 rb[4];
    auto ld = [&](int k0) {
        qa[0] = *(const uint4*)(A + (size_t)(m0 + aM) * K + k0 + aK);
        qa[1] = *(const uint4*)(A + (size_t)(m0 + aM + 64) * K + k0 + aK);
        rb[0] = *(const float4*)&B[(size_t)(k0 + 2 * bP) * N + n0 + bN4];
        rb[1] = *(const float4*)&B[(size_t)(k0 + 2 * bP + 1) * N + n0 + bN4];
        rb[2] = *(const float4*)&B[(size_t)(k0 + 2 * bP + 16) * N + n0 + bN4];
        rb[3] = *(const float4*)&B[(size_t)(k0 + 2 * bP + 17) * N + n0 + bN4];
    };
    auto sts = [&](int bf) {
        uint32_t (*A_)[PA] = As[bf];
        uint32_t (*B_)[PB] = Bs[bf];
        A_[aW + 0][aM] = qa[0].x; A_[aW + 1][aM] = qa[0].y;
        A_[aW + 2][aM] = qa[0].z; A_[aW + 3][aM] = qa[0].w;
        A_[aW + 0][aM + 64] = qa[1].x; A_[aW + 1][aM + 64] = qa[1].y;
        A_[aW + 2][aM + 64] = qa[1].z; A_[aW + 3][aM + 64] = qa[1].w;
        *(uint4*)&B_[bP][bN4] = pk4(rb[0], rb[1]);
        *(uint4*)&B_[bP + 8][bN4] = pk4(rb[2], rb[3]);
    };

    float acc[4][4][4] = {};
    const int nIters = K / BKE;
    ld(0);
    sts(0);
    __syncthreads();
    for (int it = 0; it < nIters; it++) {
        if (it + 1 < nIters) ld((it + 1) * BKE);
        mma_compute(As[it & 1], Bs[it & 1], lane, wm, wn, acc);
        if (it + 1 < nIters) sts((it + 1) & 1);
        __syncthreads();
    }
    const int c4 = lane & 3, g8 = lane >> 2;
#pragma unroll
    for (int mi = 0; mi < 4; mi++)
#pragma unroll
        for (int ni = 0; ni < 4; ni++) {
            int row = m0 + wm + mi * 16 + g8;
            int col = n0 + wn + ni * 8 + 2 * c4;
            *(uint32_t*)&C[(size_t)row * N + col] = pk(acc[mi][ni][0], acc[mi][ni][1]);
            *(uint32_t*)&C[(size_t)(row + 8) * N + col] = pk(acc[mi][ni][2], acc[mi][ni][3]);
        }
}

// Step 7: atte_bf16 = beta_bf16^T @ criteria_f32 (TN, batched; A stored (K, lda)).
__global__ __launch_bounds__(256) void mm_atte(
    const __nv_bfloat16* __restrict__ A, const float* __restrict__ B,
    __nv_bfloat16* __restrict__ C, int N, int K, int lda, size_t sA, size_t sB, size_t sC)
{
    __shared__ uint32_t As[2][16][PA];
    __shared__ uint32_t Bs[2][16][PB];
    const int tid = threadIdx.x;
    const int lane = tid & 31, wid = tid >> 5;
    const int wm = (wid & 1) * 64, wn = (wid >> 1) * 32;
    const int m0 = blockIdx.y * BM, n0 = blockIdx.x * BN;
    A += (size_t)blockIdx.z * sA;
    B += (size_t)blockIdx.z * sB;
    C += (size_t)blockIdx.z * sC;
    const int xM4 = (tid & 31) * 4, xP = tid >> 5;

    uint2 pa[4];
    float4 rb[4];
    auto ld = [&](int k0) {
        pa[0] = *(const uint2*)(A + (size_t)(k0 + 2 * xP) * lda + m0 + xM4);
        pa[1] = *(const uint2*)(A + (size_t)(k0 + 2 * xP + 1) * lda + m0 + xM4);
        pa[2] = *(const uint2*)(A + (size_t)(k0 + 2 * xP + 16) * lda + m0 + xM4);
        pa[3] = *(const uint2*)(A + (size_t)(k0 + 2 * xP + 17) * lda + m0 + xM4);
        rb[0] = *(const float4*)&B[(size_t)(k0 + 2 * xP) * N + n0 + xM4];
        rb[1] = *(const float4*)&B[(size_t)(k0 + 2 * xP + 1) * N + n0 + xM4];
        rb[2] = *(const float4*)&B[(size_t)(k0 + 2 * xP + 16) * N + n0 + xM4];
        rb[3] = *(const float4*)&B[(size_t)(k0 + 2 * xP + 17) * N + n0 + xM4];
    };
    auto sts = [&](int bf) {
        uint32_t (*A_)[PA] = As[bf];
        uint32_t (*B_)[PB] = Bs[bf];
        *(uint4*)&A_[xP][xM4] = make_uint4(
            prmt(pa[0].x, pa[1].x, 0x5410), prmt(pa[0].x, pa[1].x, 0x7632),
            prmt(pa[0].y, pa[1].y, 0x5410), prmt(pa[0].y, pa[1].y, 0x7632));
        *(uint4*)&A_[xP + 8][xM4] = make_uint4(
            prmt(pa[2].x, pa[3].x, 0x5410), prmt(pa[2].x, pa[3].x, 0x7632),
            prmt(pa[2].y, pa[3].y, 0x5410), prmt(pa[2].y, pa[3].y, 0x7632));
        *(uint4*)&B_[xP][xM4] = pk4(rb[0], rb[1]);
        *(uint4*)&B_[xP + 8][xM4] = pk4(rb[2], rb[3]);
    };

    float acc[4][4][4] = {};
    const int nIters = K / BKE;
    ld(0);
    sts(0);
    __syncthreads();
    for (int it = 0; it < nIters; it++) {
        if (it + 1 < nIters) ld((it + 1) * BKE);
        mma_compute(As[it & 1], Bs[it & 1], lane, wm, wn, acc);
        if (it + 1 < nIters) sts((it + 1) & 1);
        __syncthreads();
    }
    const int c4 = lane & 3, g8 = lane >> 2;
#pragma unroll
    for (int mi = 0; mi < 4; mi++)
#pragma unroll
        for (int ni = 0; ni < 4; ni++) {
            int row = m0 + wm + mi * 16 + g8;
            int col = n0 + wn + ni * 8 + 2 * c4;
            *(uint32_t*)&C[(size_t)row * N + col] = pk(acc[mi][ni][0], acc[mi][ni][1]);
            *(uint32_t*)&C[(size_t)(row + 8) * N + col] = pk(acc[mi][ni][2], acc[mi][ni][3]);
        }
}

// Step 8: r[b,n] += sum_m relu( [X1_bf16|X2_f32][m,:] @ Wr + br )[n]
__global__ __launch_bounds__(256) void mm_concat_rs(
    const __nv_bfloat16* __restrict__ X1, const float* __restrict__ X2,
    const float* __restrict__ Wr, const float* __restrict__ br,
    float* __restrict__ r, int L)
{
    __shared__ uint32_t As[2][16][PA];
    __shared__ uint32_t Bs[2][16][PB];
    __shared__ float colsum[BN];
    const int tid = threadIdx.x;
    const int lane = tid & 31, wid = tid >> 5;
    const int wm = (wid & 1) * 64, wn = (wid >> 1) * 32;
    const int b = blockIdx.z;
    const int m0 = blockIdx.y * BM, n0 = blockIdx.x * BN;
    const __nv_bfloat16* A1 = X1 + (size_t)b * L * DD;
    const float* A2 = X2 + (size_t)b * L * DD;
    if (tid < BN) colsum[tid] = 0.0f;
    const int aM = tid >> 2, aK = (tid & 3) * 8, aW = (tid & 3) * 4;
    const int bN4 = (tid & 31) * 4, bP = tid >> 5;

    uint32_t wa[8];
    float4 rb[4];
    auto ld = [&](int k0) {
        if (k0 < DD) {
            uint4 q0 = *(const uint4*)(A1 + (size_t)(m0 + aM) * DD + k0 + aK);
            uint4 q1 = *(const uint4*)(A1 + (size_t)(m0 + aM + 64) * DD + k0 + aK);
            wa[0] = q0.x; wa[1] = q0.y; wa[2] = q0.z; wa[3] = q0.w;
            wa[4] = q1.x; wa[5] = q1.y; wa[6] = q1.z; wa[7] = q1.w;
        } else {
            int kk = k0 - DD;
            float4 f0 = *(const float4*)&A2[(size_t)(m0 + aM) * DD + kk + aK];
            float4 f1 = *(const float4*)&A2[(size_t)(m0 + aM) * DD + kk + aK + 4];
            float4 f2 = *(const float4*)&A2[(size_t)(m0 + aM + 64) * DD + kk + aK];
            float4 f3 = *(const float4*)&A2[(size_t)(m0 + aM + 64) * DD + kk + aK + 4];
            wa[0] = pk(f0.x, f0.y); wa[1] = pk(f0.z, f0.w);
            wa[2] = pk(f1.x, f1.y); wa[3] = pk(f1.z, f1.w);
            wa[4] = pk(f2.x, f2.y); wa[5] = pk(f2.z, f2.w);
            wa[6] = pk(f3.x, f3.y); wa[7] = pk(f3.z, f3.w);
        }
        rb[0] = *(const float4*)&Wr[(size_t)(k0 + 2 * bP) * DD + n0 + bN4];
        rb[1] = *(const float4*)&Wr[(size_t)(k0 + 2 * bP + 1) * DD + n0 + bN4];
        rb[2] = *(const float4*)&Wr[(size_t)(k0 + 2 * bP + 16) * DD + n0 + bN4];
        rb[3] = *(const float4*)&Wr[(size_t)(k0 + 2 * bP + 17) * DD + n0 + bN4];
    };
    auto sts = [&](int bf) {
        uint32_t (*A_)[PA] = As[bf];
        uint32_t (*B_)[PB] = Bs[bf];
        A_[aW + 0][aM] = wa[0]; A_[aW + 1][aM] = wa[1];
        A_[aW + 2][aM] = wa[2]; A_[aW + 3][aM] = wa[3];
        A_[aW + 0][aM + 64] = wa[4]; A_[aW + 1][aM + 64] = wa[5];
        A_[aW + 2][aM + 64] = wa[6]; A_[aW + 3][aM + 64] = wa[7];
        *(uint4*)&B_[bP][bN4] = pk4(rb[0], rb[1]);
        *(uint4*)&B_[bP + 8][bN4] = pk4(rb[2], rb[3]);
    };

    float acc[4][4][4] = {};
    const int nIters = (2 * DD) / BKE;
    ld(0);
    sts(0);
    __syncthreads();
    for (int it = 0; it < nIters; it++) {
        if (it + 1 < nIters) ld((it + 1) * BKE);
        mma_compute(As[it & 1], Bs[it & 1], lane, wm, wn, acc);
        if (it + 1 < nIters) sts((it + 1) & 1);
        __syncthreads();
    }
    const int c4 = lane & 3;
#pragma unroll
    for (int ni = 0; ni < 4; ni++) {
        int col = wn + ni * 8 + 2 * c4;
        float b0 = br[n0 + col], b1 = br[n0 + col + 1];
        float s0 = 0.f, s1 = 0.f;
#pragma unroll
        for (int mi = 0; mi < 4; mi++) {
            s0 += fmaxf(acc[mi][ni][0] + b0, 0.f) + fmaxf(acc[mi][ni][2] + b0, 0.f);
            s1 += fmaxf(acc[mi][ni][1] + b1, 0.f) + fmaxf(acc[mi][ni][3] + b1, 0.f);
        }
        atomicAdd(&colsum[col], s0);
        atomicAdd(&colsum[col + 1], s1);
    }
    __syncthreads();
    if (tid < BN) atomicAdd(&r[(size_t)b * DD + n0 + tid], colsum[tid]);
}

// ---------------- softmax + head (identical to R7) ----------------
__global__ void beta_kernel(const float* __restrict__ align_, __nv_bfloat16* __restrict__ beta,
                            const int* __restrict__ cmask)
{
    const int b = blockIdx.y;
    const int e = blockIdx.x * 32 + threadIdx.x;
    const int tx = threadIdx.x, ty = threadIdx.y;
    const float* base = align_ + (size_t)b * LC * LE + e;
    __nv_bfloat16* outb = beta + (size_t)b * LC * LE + e;
    float vals[LC / 8];
    float mx = -INFINITY;
#pragma unroll
    for (int i = 0; i < LC / 8; i++) {
        int l = ty + i * 8;
        float v = base[(size_t)l * LE] + (1.0f - (float)cmask[b * LC + l]) * NEGV;
        vals[i] = v;
        mx = fmaxf(mx, v);
    }
    __shared__ float red[8][32];
    red[ty][tx] = mx;
    __syncthreads();
    if (ty == 0) {
        float m2 = red[0][tx];
#pragma unroll
        for (int i = 1; i < 8; i++) m2 = fmaxf(m2, red[i][tx]);
        red[0][tx] = m2;
    }
    __syncthreads();
    mx = red[0][tx];
    __syncthreads();
    float s = 0.0f;
#pragma unroll
    for (int i = 0; i < LC / 8; i++) { vals[i] = expf(vals[i] - mx); s += vals[i]; }
    red[ty][tx] = s;
    __syncthreads();
    if (ty == 0) {
        float s2 = 0.0f;
#pragma unroll
        for (int i = 0; i < 8; i++) s2 += red[i][tx];
        red[0][tx] = s2;
    }
    __syncthreads();
    float inv = 1.0f / red[0][tx];
#pragma unroll
    for (int i = 0; i < LC / 8; i++) {
        int l = ty + i * 8;
        outb[(size_t)l * LE] = __float2bfloat16_rn(vals[i] * inv);
    }
}

__global__ void alpha_kernel(const float* __restrict__ align_, __nv_bfloat16* __restrict__ alpha,
                             const int* __restrict__ emask)
{
    const int b = blockIdx.y, l = blockIdx.x, t = threadIdx.x;
    const float* row = align_ + ((size_t)b * LC + l) * LE;
    __nv_bfloat16* arow = alpha + ((size_t)b * LC + l) * LE;
    float v[4];
    float mx = -INFINITY;
#pragma unroll
    for (int j = 0; j < 4; j++) {
        int e = t + j * 256;
        v[j] = row[e] + (1.0f - (float)emask[b * LE + e]) * NEGV;
        mx = fmaxf(mx, v[j]);
    }
    __shared__ float sm[256];
    sm[t] = mx;
    __syncthreads();
    for (int s = 128; s > 0; s >>= 1) { if (t < s) sm[t] = fmaxf(sm[t], sm[t + s]); __syncthreads(); }
    mx = sm[0];
    __syncthreads();
    float sum = 0.0f;
#pragma unroll
    for (int j = 0; j < 4; j++) { v[j] = expf(v[j] - mx); sum += v[j]; }
    sm[t] = sum;
    __syncthreads();
    for (int s = 128; s > 0; s >>= 1) { if (t < s) sm[t] += sm[t + s]; __syncthreads(); }
    float inv = 1.0f / sm[0];
#pragma unroll
    for (int j = 0; j < 4; j++) arow[t + j * 256] = __float2bfloat16_rn(v[j] * inv);
}

__global__ void head_kernel(const float* __restrict__ r1, const float* __restrict__ r2,
                            const float* __restrict__ Wm, const float* __restrict__ bm,
                            const float* __restrict__ Wo, const float* __restrict__ bo,
                            float* __restrict__ out)
{
    const int b = blockIdx.x, t = threadIdx.x;
    __shared__ float mv[4 * DD];
    __shared__ float outacc[3];
    if (t < DD) {
        float a = r1[(size_t)b * DD + t], c = r2[(size_t)b * DD + t];
        mv[t] = a; mv[DD + t] = c; mv[2 * DD + t] = a * c; mv[3 * DD + t] = a - c;
    }
    if (t < 3) outacc[t] = 0.0f;
    __syncthreads();
    float acc = bm[t];
#pragma unroll 8
    for (int k = 0; k < 4 * DD; k++) acc = fmaf(mv[k], Wm[(size_t)k * MM + t], acc);
    float h = fmaxf(acc, 0.0f);
#pragma unroll
    for (int i = 0; i < 3; i++) atomicAdd(&outacc[i], h * Wo[(size_t)t * 3 + i]);
    __syncthreads();
    if (t < 3) out[(size_t)b * 3 + t] = outacc[t] + bo[t];
}

// ---------------- launch (identical to R7) ----------------
extern "C" void kernel_launch(void* const* d_in, const int* in_sizes, int n_in,
                              void* d_out, int out_size)
{
    const float* criteria = (const float*)d_in[0];
    const float* ehr      = (const float*)d_in[1];
    const int*   cmask    = (const int*)d_in[2];
    const int*   emask    = (const int*)d_in[3];
    const float* Wa       = (const float*)d_in[4];
    const float* ba       = (const float*)d_in[5];
    const float* Wr       = (const float*)d_in[6];
    const float* br       = (const float*)d_in[7];
    const float* Wm       = (const float*)d_in[8];
    const float* bm       = (const float*)d_in[9];
    const float* Wo       = (const float*)d_in[10];
    const float* bo       = (const float*)d_in[11];
    float* out = (float*)d_out;

    float* base;
    cudaGetSymbolAddress((void**)&base, g_scratch);
    __nv_bfloat16* p_c     = (__nv_bfloat16*)(base + OFF_CB);
    __nv_bfloat16* p_e     = (__nv_bfloat16*)(base + OFF_EB);
    float*         p_align = base + OFF_ALIGN;
    __nv_bfloat16* p_beta  = (__nv_bfloat16*)(base + OFF_EB);
    __nv_bfloat16* p_alpha = (__nv_bfloat16*)(base + OFF_ALPHA);
    __nv_bfloat16* p_attc  = (__nv_bfloat16*)(base + OFF_CB);
    __nv_bfloat16* p_atte  = (__nv_bfloat16*)(base + OFF_ATTE);
    float*         p_r1    = base + OFF_R1;
    float*         p_r2    = base + OFF_R2;

    mm_proj<<<dim3(DD / BN, (BB * LC) / BM), 256>>>(criteria, Wa, ba, p_c, DD, DD);
    mm_proj<<<dim3(DD / BN, (BB * LE) / BM), 256>>>(ehr, Wa, ba, p_e, DD, DD);
    mm_align<<<dim3(LE / BN, LC / BM, BB), 256>>>(
        p_c, p_e, p_align, LE, DD,
        (size_t)LC * DD, (size_t)LE * DD, (size_t)LC * LE);
    beta_kernel<<<dim3(LE / 32, BB), dim3(32, 8)>>>(p_align, p_beta, cmask);
    alpha_kernel<<<dim3(LC, BB), 256>>>(p_align, p_alpha, emask);
    mm_attc<<<dim3(DD / BN, LC / BM, BB), 256>>>(
        p_alpha, ehr, p_attc, DD, LE,
        (size_t)LC * LE, (size_t)LE * DD, (size_t)LC * DD);
    mm_atte<<<dim3(DD / BN, LE / BM, BB), 256>>>(
        p_beta, criteria, p_atte, DD, LC, LE,
        (size_t)LC * LE, (size_t)LC * DD, (size_t)LE * DD);
    cudaMemsetAsync(p_r1, 0, (size_t)2 * BB * DD * sizeof(float));
    mm_concat_rs<<<dim3(DD / BN, LC / BM, BB), 256>>>(p_attc, criteria, Wr, br, p_r1, LC);
    mm_concat_rs<<<dim3(DD / BN, LE / BM, BB), 256>>>(p_atte, ehr, Wr, br, p_r2, LE);
    head_kernel<<<BB, MM>>>(p_r1, p_r2, Wm, bm, Wo, bo, out);
}

// round 14
// speedup vs baseline: 1.1081x; 1.0307x over previous
#include <cuda_runtime.h>
#include <cuda_bf16.h>
#include <math.h>
#include <stdint.h>

#define BB 128
#define LC 256
#define LE 1024
#define DD 256
#define MM 512
#define NEGV (-1e9f)

#define BM 128
#define BN 128
#define BKE 32
#define PA 132
#define PB 132

// ---------------- scratch (aliased; float units) ----------------
#define HCLD ((size_t)BB * LC * DD / 2)
#define HLED ((size_t)BB * LE * DD / 2)
#define HLCE ((size_t)BB * LC * LE / 2)
#define OFF_CB    ((size_t)0)                          // c bf16 -> attc
#define OFF_EB    (OFF_CB + HCLD)                      // e bf16 -> beta
#define OFF_ALIGN (OFF_EB + HLED)                      // align f32
#define OFF_ALPHA (OFF_ALIGN + (size_t)BB * LC * LE)   // alpha bf16 -> atte (alias)
#define OFF_EHRB  (OFF_ALPHA + HLCE)                   // ehr bf16
#define OFF_CRITB (OFF_EHRB + HLED)                    // criteria bf16
#define OFF_WAB   (OFF_CRITB + HCLD)
#define OFF_WRB   (OFF_WAB + (size_t)DD * DD / 2)
#define OFF_R1    (OFF_WRB + (size_t)DD * DD)
#define OFF_R2    (OFF_R1 + (size_t)BB * DD)
#define SCRATCH_FLOATS (OFF_R2 + (size_t)BB * DD)
__device__ float g_scratch[SCRATCH_FLOATS];   // ~353 MB

// ---------------- helpers ----------------
__device__ __forceinline__ uint32_t pk(float lo, float hi) {
    __nv_bfloat162 h = __floats2bfloat162_rn(lo, hi);
    return *reinterpret_cast<uint32_t*>(&h);
}
__device__ __forceinline__ uint32_t prmt(uint32_t a, uint32_t b, uint32_t c) {
    uint32_t d;
    asm("prmt.b32 %0, %1, %2, %3;" : "=r"(d) : "r"(a), "r"(b), "r"(c));
    return d;
}
__device__ __forceinline__ void mma_bf16(float* c, const uint32_t* a, const uint32_t* b) {
    asm volatile(
        "mma.sync.aligned.m16n8k16.row.col.f32.bf16.bf16.f32 "
        "{%0,%1,%2,%3}, {%4,%5,%6,%7}, {%8,%9}, {%0,%1,%2,%3};"
        : "+f"(c[0]), "+f"(c[1]), "+f"(c[2]), "+f"(c[3])
        : "r"(a[0]), "r"(a[1]), "r"(a[2]), "r"(a[3]), "r"(b[0]), "r"(b[1]));
}
__device__ __forceinline__ void mma_compute(
    const uint32_t (*As)[PA], const uint32_t (*Bs)[PB],
    int lane, int wm, int wn, float acc[4][4][4])
{
    const int c4 = lane & 3;
    const int g8 = lane >> 2;
#pragma unroll
    for (int ks = 0; ks < 16; ks += 8) {
        uint32_t af[4][4];
#pragma unroll
        for (int mi = 0; mi < 4; mi++) {
            int mrow = wm + mi * 16 + g8;
            af[mi][0] = As[ks + c4][mrow];
            af[mi][1] = As[ks + c4][mrow + 8];
            af[mi][2] = As[ks + c4 + 4][mrow];
            af[mi][3] = As[ks + c4 + 4][mrow + 8];
        }
        uint32_t bf[4][2];
#pragma unroll
        for (int ni = 0; ni < 4; ni++) {
            int ncol = wn + ni * 8 + g8;
            bf[ni][0] = Bs[ks + c4][ncol];
            bf[ni][1] = Bs[ks + c4 + 4][ncol];
        }
#pragma unroll
        for (int mi = 0; mi < 4; mi++)
#pragma unroll
            for (int ni = 0; ni < 4; ni++)
                mma_bf16(acc[mi][ni], af[mi], bf[ni]);
    }
}

// f32 -> bf16 elementwise, vec8. n divisible by 8.
__global__ void convf2b(const float* __restrict__ in, __nv_bfloat16* __restrict__ out, size_t n)
{
    size_t i = ((size_t)blockIdx.x * blockDim.x + threadIdx.x) * 8;
    if (i < n) {
        float4 a = *(const float4*)(in + i), b = *(const float4*)(in + i + 4);
        *(uint4*)(out + i) = make_uint4(pk(a.x, a.y), pk(a.z, a.w), pk(b.x, b.y), pk(b.z, b.w));
    }
}

// ---------------- GEMM kernels (all-bf16 operands, double-buffered) ----------------

// Steps 1,2: C_bf16 = relu(A_bf16 @ B_bf16 + bias). A (M,K) rm, B (K,N) rm.
__global__ __launch_bounds__(256) void mm_proj(
    const __nv_bfloat16* __restrict__ A, const __nv_bfloat16* __restrict__ B,
    const float* __restrict__ bias, __nv_bfloat16* __restrict__ C, int N, int K)
{
    __shared__ uint32_t As[2][16][PA];
    __shared__ uint32_t Bs[2][16][PB];
    const int tid = threadIdx.x;
    const int lane = tid & 31, wid = tid >> 5;
    const int wm = (wid & 1) * 64, wn = (wid >> 1) * 32;
    const int m0 = blockIdx.y * BM, n0 = blockIdx.x * BN;
    const int aM = tid >> 2, aK = (tid & 3) * 8, aW = (tid & 3) * 4;
    const int bN4 = (tid & 31) * 4, bP = tid >> 5;

    uint4 qa[2];
    uint2 rb[4];
    auto ld = [&](int k0) {
        qa[0] = *(const uint4*)(A + (size_t)(m0 + aM) * K + k0 + aK);
        qa[1] = *(const uint4*)(A + (size_t)(m0 + aM + 64) * K + k0 + aK);
        rb[0] = *(const uint2*)(B + (size_t)(k0 + 2 * bP) * N + n0 + bN4);
        rb[1] = *(const uint2*)(B + (size_t)(k0 + 2 * bP + 1) * N + n0 + bN4);
        rb[2] = *(const uint2*)(B + (size_t)(k0 + 2 * bP + 16) * N + n0 + bN4);
        rb[3] = *(const uint2*)(B + (size_t)(k0 + 2 * bP + 17) * N + n0 + bN4);
    };
    auto sts = [&](int bf) {
        uint32_t (*A_)[PA] = As[bf];
        uint32_t (*B_)[PB] = Bs[bf];
        A_[aW + 0][aM] = qa[0].x; A_[aW + 1][aM] = qa[0].y;
        A_[aW + 2][aM] = qa[0].z; A_[aW + 3][aM] = qa[0].w;
        A_[aW + 0][aM + 64] = qa[1].x; A_[aW + 1][aM + 64] = qa[1].y;
        A_[aW + 2][aM + 64] = qa[1].z; A_[aW + 3][aM + 64] = qa[1].w;
        *(uint4*)&B_[bP][bN4] = make_uint4(
            prmt(rb[0].x, rb[1].x, 0x5410), prmt(rb[0].x, rb[1].x, 0x7632),
            prmt(rb[0].y, rb[1].y, 0x5410), prmt(rb[0].y, rb[1].y, 0x7632));
        *(uint4*)&B_[bP + 8][bN4] = make_uint4(
            prmt(rb[2].x, rb[3].x, 0x5410), prmt(rb[2].x, rb[3].x, 0x7632),
            prmt(rb[2].y, rb[3].y, 0x5410), prmt(rb[2].y, rb[3].y, 0x7632));
    };

    float acc[4][4][4] = {};
    const int nIters = K / BKE;
    ld(0);
    sts(0);
    __syncthreads();
    for (int it = 0; it < nIters; it++) {
        if (it + 1 < nIters) ld((it + 1) * BKE);
        mma_compute(As[it & 1], Bs[it & 1], lane, wm, wn, acc);
        if (it + 1 < nIters) sts((it + 1) & 1);
        __syncthreads();
    }
    const int c4 = lane & 3, g8 = lane >> 2;
#pragma unroll
    for (int mi = 0; mi < 4; mi++)
#pragma unroll
        for (int ni = 0; ni < 4; ni++) {
            int row = m0 + wm + mi * 16 + g8;
            int col = n0 + wn + ni * 8 + 2 * c4;
            float b0 = bias[col], b1 = bias[col + 1];
            *(uint32_t*)&C[(size_t)row * N + col] =
                pk(fmaxf(acc[mi][ni][0] + b0, 0.f), fmaxf(acc[mi][ni][1] + b1, 0.f));
            *(uint32_t*)&C[(size_t)(row + 8) * N + col] =
                pk(fmaxf(acc[mi][ni][2] + b0, 0.f), fmaxf(acc[mi][ni][3] + b1, 0.f));
        }
}

// Step 3: align_f32 = c_bf16 @ e_bf16^T (NT, batched). Unchanged from R12.
__global__ __launch_bounds__(256) void mm_align(
    const __nv_bfloat16* __restrict__ A, const __nv_bfloat16* __restrict__ Bm,
    float* __restrict__ C, int N, int K, size_t sA, size_t sB, size_t sC)
{
    __shared__ uint32_t As[2][16][PA];
    __shared__ uint32_t Bs[2][16][PB];
    const int tid = threadIdx.x;
    const int lane = tid & 31, wid = tid >> 5;
    const int wm = (wid & 1) * 64, wn = (wid >> 1) * 32;
    const int m0 = blockIdx.y * BM, n0 = blockIdx.x * BN;
    A += (size_t)blockIdx.z * sA;
    Bm += (size_t)blockIdx.z * sB;
    C += (size_t)blockIdx.z * sC;
    const int aM = tid >> 2, aK = (tid & 3) * 8, aW = (tid & 3) * 4;

    uint4 qa[2], qb[2];
    auto ld = [&](int k0) {
        qa[0] = *(const uint4*)(A + (size_t)(m0 + aM) * K + k0 + aK);
        qa[1] = *(const uint4*)(A + (size_t)(m0 + aM + 64) * K + k0 + aK);
        qb[0] = *(const uint4*)(Bm + (size_t)(n0 + aM) * K + k0 + aK);
        qb[1] = *(const uint4*)(Bm + (size_t)(n0 + aM + 64) * K + k0 + aK);
    };
    auto sts = [&](int bf) {
        uint32_t (*A_)[PA] = As[bf];
        uint32_t (*B_)[PB] = Bs[bf];
        A_[aW + 0][aM] = qa[0].x; A_[aW + 1][aM] = qa[0].y;
        A_[aW + 2][aM] = qa[0].z; A_[aW + 3][aM] = qa[0].w;
        A_[aW + 0][aM + 64] = qa[1].x; A_[aW + 1][aM + 64] = qa[1].y;
        A_[aW + 2][aM + 64] = qa[1].z; A_[aW + 3][aM + 64] = qa[1].w;
        B_[aW + 0][aM] = qb[0].x; B_[aW + 1][aM] = qb[0].y;
        B_[aW + 2][aM] = qb[0].z; B_[aW + 3][aM] = qb[0].w;
        B_[aW + 0][aM + 64] = qb[1].x; B_[aW + 1][aM + 64] = qb[1].y;
        B_[aW + 2][aM + 64] = qb[1].z; B_[aW + 3][aM + 64] = qb[1].w;
    };

    float acc[4][4][4] = {};
    const int nIters = K / BKE;
    ld(0);
    sts(0);
    __syncthreads();
    for (int it = 0; it < nIters; it++) {
        if (it + 1 < nIters) ld((it + 1) * BKE);
        mma_compute(As[it & 1], Bs[it & 1], lane, wm, wn, acc);
        if (it + 1 < nIters) sts((it + 1) & 1);
        __syncthreads();
    }
    const int c4 = lane & 3, g8 = lane >> 2;
#pragma unroll
    for (int mi = 0; mi < 4; mi++)
#pragma unroll
        for (int ni = 0; ni < 4; ni++) {
            int row = m0 + wm + mi * 16 + g8;
            int col = n0 + wn + ni * 8 + 2 * c4;
            *(float2*)&C[(size_t)row * N + col] = make_float2(acc[mi][ni][0], acc[mi][ni][1]);
            *(float2*)&C[(size_t)(row + 8) * N + col] = make_float2(acc[mi][ni][2], acc[mi][ni][3]);
        }
}

// Step 6: attc_bf16 = alpha_bf16 @ ehrB_bf16 (NN, batched).
__global__ __launch_bounds__(256) void mm_attc(
    const __nv_bfloat16* __restrict__ A, const __nv_bfloat16* __restrict__ B,
    __nv_bfloat16* __restrict__ C, int N, int K, size_t sA, size_t sB, size_t sC)
{
    __shared__ uint32_t As[2][16][PA];
    __shared__ uint32_t Bs[2][16][PB];
    const int tid = threadIdx.x;
    const int lane = tid & 31, wid = tid >> 5;
    const int wm = (wid & 1) * 64, wn = (wid >> 1) * 32;
    const int m0 = blockIdx.y * BM, n0 = blockIdx.x * BN;
    A += (size_t)blockIdx.z * sA;
    B += (size_t)blockIdx.z * sB;
    C += (size_t)blockIdx.z * sC;
    const int aM = tid >> 2, aK = (tid & 3) * 8, aW = (tid & 3) * 4;
    const int bN4 = (tid & 31) * 4, bP = tid >> 5;

    uint4 qa[2];
    uint2 rb[4];
    auto ld = [&](int k0) {
        qa[0] = *(const uint4*)(A + (size_t)(m0 + aM) * K + k0 + aK);
        qa[1] = *(const uint4*)(A + (size_t)(m0 + aM + 64) * K + k0 + aK);
        rb[0] = *(const uint2*)(B + (size_t)(k0 + 2 * bP) * N + n0 + bN4);
        rb[1] = *(const uint2*)(B + (size_t)(k0 + 2 * bP + 1) * N + n0 + bN4);
        rb[2] = *(const uint2*)(B + (size_t)(k0 + 2 * bP + 16) * N + n0 + bN4);
        rb[3] = *(const uint2*)(B + (size_t)(k0 + 2 * bP + 17) * N + n0 + bN4);
    };
    auto sts = [&](int bf) {
        uint32_t (*A_)[PA] = As[bf];
        uint32_t (*B_)[PB] = Bs[bf];
        A_[aW + 0][aM] = qa[0].x; A_[aW + 1][aM] = qa[0].y;
        A_[aW + 2][aM] = qa[0].z; A_[aW + 3][aM] = qa[0].w;
        A_[aW + 0][aM + 64] = qa[1].x; A_[aW + 1][aM + 64] = qa[1].y;
        A_[aW + 2][aM + 64] = qa[1].z; A_[aW + 3][aM + 64] = qa[1].w;
        *(uint4*)&B_[bP][bN4] = make_uint4(
            prmt(rb[0].x, rb[1].x, 0x5410), prmt(rb[0].x, rb[1].x, 0x7632),
            prmt(rb[0].y, rb[1].y, 0x5410), prmt(rb[0].y, rb[1].y, 0x7632));
        *(uint4*)&B_[bP + 8][bN4] = make_uint4(
            prmt(rb[2].x, rb[3].x, 0x5410), prmt(rb[2].x, rb[3].x, 0x7632),
            prmt(rb[2].y, rb[3].y, 0x5410), prmt(rb[2].y, rb[3].y, 0x7632));
    };

    float acc[4][4][4] = {};
    const int nIters = K / BKE;
    ld(0);
    sts(0);
    __syncthreads();
    for (int it = 0; it < nIters; it++) {
        if (it + 1 < nIters) ld((it + 1) * BKE);
        mma_compute(As[it & 1], Bs[it & 1], lane, wm, wn, acc);
        if (it + 1 < nIters) sts((it + 1) & 1);
        __syncthreads();
    }
    const int c4 = lane & 3, g8 = lane >> 2;
#pragma unroll
    for (int mi = 0; mi < 4; mi++)
#pragma unroll
        for (int ni = 0; ni < 4; ni++) {
            int row = m0 + wm + mi * 16 + g8;
            int col = n0 + wn + ni * 8 + 2 * c4;
            *(uint32_t*)&C[(size_t)row * N + col] = pk(acc[mi][ni][0], acc[mi][ni][1]);
            *(uint32_t*)&C[(size_t)(row + 8) * N + col] = pk(acc[mi][ni][2], acc[mi][ni][3]);
        }
}

// Step 7: atte_bf16 = beta_bf16^T @ critB_bf16 (TN, batched; A stored (K, lda)).
__global__ __launch_bounds__(256) void mm_atte(
    const __nv_bfloat16* __restrict__ A, const __nv_bfloat16* __restrict__ B,
    __nv_bfloat16* __restrict__ C, int N, int K, int lda, size_t sA, size_t sB, size_t sC)
{
    __shared__ uint32_t As[2][16][PA];
    __shared__ uint32_t Bs[2][16][PB];
    const int tid = threadIdx.x;
    const int lane = tid & 31, wid = tid >> 5;
    const int wm = (wid & 1) * 64, wn = (wid >> 1) * 32;
    const int m0 = blockIdx.y * BM, n0 = blockIdx.x * BN;
    A += (size_t)blockIdx.z * sA;
    B += (size_t)blockIdx.z * sB;
    C += (size_t)blockIdx.z * sC;
    const int xM4 = (tid & 31) * 4, xP = tid >> 5;

    uint2 pa[4], rb[4];
    auto ld = [&](int k0) {
        pa[0] = *(const uint2*)(A + (size_t)(k0 + 2 * xP) * lda + m0 + xM4);
        pa[1] = *(const uint2*)(A + (size_t)(k0 + 2 * xP + 1) * lda + m0 + xM4);
        pa[2] = *(const uint2*)(A + (size_t)(k0 + 2 * xP + 16) * lda + m0 + xM4);
        pa[3] = *(const uint2*)(A + (size_t)(k0 + 2 * xP + 17) * lda + m0 + xM4);
        rb[0] = *(const uint2*)(B + (size_t)(k0 + 2 * xP) * N + n0 + xM4);
        rb[1] = *(const uint2*)(B + (size_t)(k0 + 2 * xP + 1) * N + n0 + xM4);
        rb[2] = *(const uint2*)(B + (size_t)(k0 + 2 * xP + 16) * N + n0 + xM4);
        rb[3] = *(const uint2*)(B + (size_t)(k0 + 2 * xP + 17) * N + n0 + xM4);
    };
    auto sts = [&](int bf) {
        uint32_t (*A_)[PA] = As[bf];
        uint32_t (*B_)[PB] = Bs[bf];
        *(uint4*)&A_[xP][xM4] = make_uint4(
            prmt(pa[0].x, pa[1].x, 0x5410), prmt(pa[0].x, pa[1].x, 0x7632),
            prmt(pa[0].y, pa[1].y, 0x5410), prmt(pa[0].y, pa[1].y, 0x7632));
        *(uint4*)&A_[xP + 8][xM4] = make_uint4(
            prmt(pa[2].x, pa[3].x, 0x5410), prmt(pa[2].x, pa[3].x, 0x7632),
            prmt(pa[2].y, pa[3].y, 0x5410), prmt(pa[2].y, pa[3].y, 0x7632));
        *(uint4*)&B_[xP][xM4] = make_uint4(
            prmt(rb[0].x, rb[1].x, 0x5410), prmt(rb[0].x, rb[1].x, 0x7632),
            prmt(rb[0].y, rb[1].y, 0x5410), prmt(rb[0].y, rb[1].y, 0x7632));
        *(uint4*)&B_[xP + 8][xM4] = make_uint4(
            prmt(rb[2].x, rb[3].x, 0x5410), prmt(rb[2].x, rb[3].x, 0x7632),
            prmt(rb[2].y, rb[3].y, 0x5410), prmt(rb[2].y, rb[3].y, 0x7632));
    };

    float acc[4][4][4] = {};
    const int nIters = K / BKE;
    ld(0);
    sts(0);
    __syncthreads();
    for (int it = 0; it < nIters; it++) {
        if (it + 1 < nIters) ld((it + 1) * BKE);
        mma_compute(As[it & 1], Bs[it & 1], lane, wm, wn, acc);
        if (it + 1 < nIters) sts((it + 1) & 1);
        __syncthreads();
    }
    const int c4 = lane & 3, g8 = lane >> 2;
#pragma unroll
    for (int mi = 0; mi < 4; mi++)
#pragma unroll
        for (int ni = 0; ni < 4; ni++) {
            int row = m0 + wm + mi * 16 + g8;
            int col = n0 + wn + ni * 8 + 2 * c4;
            *(uint32_t*)&C[(size_t)row * N + col] = pk(acc[mi][ni][0], acc[mi][ni][1]);
            *(uint32_t*)&C[(size_t)(row + 8) * N + col] = pk(acc[mi][ni][2], acc[mi][ni][3]);
        }
}

// Step 8: r[b,n] += sum_m relu( [X1|X2]_bf16[m,:] @ WrB + br )[n]
__global__ __launch_bounds__(256) void mm_concat_rs(
    const __nv_bfloat16* __restrict__ X1, const __nv_bfloat16* __restrict__ X2,
    const __nv_bfloat16* __restrict__ Wr, const float* __restrict__ br,
    float* __restrict__ r, int L)
{
    __shared__ uint32_t As[2][16][PA];
    __shared__ uint32_t Bs[2][16][PB];
    __shared__ float colsum[BN];
    const int tid = threadIdx.x;
    const int lane = tid & 31, wid = tid >> 5;
    const int wm = (wid & 1) * 64, wn = (wid >> 1) * 32;
    const int b = blockIdx.z;
    const int m0 = blockIdx.y * BM, n0 = blockIdx.x * BN;
    const __nv_bfloat16* A1 = X1 + (size_t)b * L * DD;
    const __nv_bfloat16* A2 = X2 + (size_t)b * L * DD;
    if (tid < BN) colsum[tid] = 0.0f;
    const int aM = tid >> 2, aK = (tid & 3) * 8, aW = (tid & 3) * 4;
    const int bN4 = (tid & 31) * 4, bP = tid >> 5;

    uint4 qa[2];
    uint2 rb[4];
    auto ld = [&](int k0) {
        const __nv_bfloat16* src = (k0 < DD) ? A1 : A2;
        int kk = (k0 < DD) ? k0 : k0 - DD;
        qa[0] = *(const uint4*)(src + (size_t)(m0 + aM) * DD + kk + aK);
        qa[1] = *(const uint4*)(src + (size_t)(m0 + aM + 64) * DD + kk + aK);
        rb[0] = *(const uint2*)(Wr + (size_t)(k0 + 2 * bP) * DD + n0 + bN4);
        rb[1] = *(const uint2*)(Wr + (size_t)(k0 + 2 * bP + 1) * DD + n0 + bN4);
        rb[2] = *(const uint2*)(Wr + (size_t)(k0 + 2 * bP + 16) * DD + n0 + bN4);
        rb[3] = *(const uint2*)(Wr + (size_t)(k0 + 2 * bP + 17) * DD + n0 + bN4);
    };
    auto sts = [&](int bf) {
        uint32_t (*A_)[PA] = As[bf];
        uint32_t (*B_)[PB] = Bs[bf];
        A_[aW + 0][aM] = qa[0].x; A_[aW + 1][aM] = qa[0].y;
        A_[aW + 2][aM] = qa[0].z; A_[aW + 3][aM] = qa[0].w;
        A_[aW + 0][aM + 64] = qa[1].x; A_[aW + 1][aM + 64] = qa[1].y;
        A_[aW + 2][aM + 64] = qa[1].z; A_[aW + 3][aM + 64] = qa[1].w;
        *(uint4*)&B_[bP][bN4] = make_uint4(
            prmt(rb[0].x, rb[1].x, 0x5410), prmt(rb[0].x, rb[1].x, 0x7632),
            prmt(rb[0].y, rb[1].y, 0x5410), prmt(rb[0].y, rb[1].y, 0x7632));
        *(uint4*)&B_[bP + 8][bN4] = make_uint4(
            prmt(rb[2].x, rb[3].x, 0x5410), prmt(rb[2].x, rb[3].x, 0x7632),
            prmt(rb[2].y, rb[3].y, 0x5410), prmt(rb[2].y, rb[3].y, 0x7632));
    };

    float acc[4][4][4] = {};
    const int nIters = (2 * DD) / BKE;
    ld(0);
    sts(0);
    __syncthreads();
    for (int it = 0; it < nIters; it++) {
        if (it + 1 < nIters) ld((it + 1) * BKE);
        mma_compute(As[it & 1], Bs[it & 1], lane, wm, wn, acc);
        if (it + 1 < nIters) sts((it + 1) & 1);
        __syncthreads();
    }
    const int c4 = lane & 3;
#pragma unroll
    for (int ni = 0; ni < 4; ni++) {
        int col = wn + ni * 8 + 2 * c4;
        float b0 = br[n0 + col], b1 = br[n0 + col + 1];
        float s0 = 0.f, s1 = 0.f;
#pragma unroll
        for (int mi = 0; mi < 4; mi++) {
            s0 += fmaxf(acc[mi][ni][0] + b0, 0.f) + fmaxf(acc[mi][ni][2] + b0, 0.f);
            s1 += fmaxf(acc[mi][ni][1] + b1, 0.f) + fmaxf(acc[mi][ni][3] + b1, 0.f);
        }
        atomicAdd(&colsum[col], s0);
        atomicAdd(&colsum[col + 1], s1);
    }
    __syncthreads();
    if (tid < BN) atomicAdd(&r[(size_t)b * DD + n0 + tid], colsum[tid]);
}

// ---------------- softmax + head (identical to R12) ----------------
__global__ void beta_kernel(const float* __restrict__ align_, __nv_bfloat16* __restrict__ beta,
                            const int* __restrict__ cmask)
{
    const int b = blockIdx.y;
    const int e = blockIdx.x * 32 + threadIdx.x;
    const int tx = threadIdx.x, ty = threadIdx.y;
    const float* base = align_ + (size_t)b * LC * LE + e;
    __nv_bfloat16* outb = beta + (size_t)b * LC * LE + e;
    float vals[LC / 8];
    float mx = -INFINITY;
#pragma unroll
    for (int i = 0; i < LC / 8; i++) {
        int l = ty + i * 8;
        float v = base[(size_t)l * LE] + (1.0f - (float)cmask[b * LC + l]) * NEGV;
        vals[i] = v;
        mx = fmaxf(mx, v);
    }
    __shared__ float red[8][32];
    red[ty][tx] = mx;
    __syncthreads();
    if (ty == 0) {
        float m2 = red[0][tx];
#pragma unroll
        for (int i = 1; i < 8; i++) m2 = fmaxf(m2, red[i][tx]);
        red[0][tx] = m2;
    }
    __syncthreads();
    mx = red[0][tx];
    __syncthreads();
    float s = 0.0f;
#pragma unroll
    for (int i = 0; i < LC / 8; i++) { vals[i] = expf(vals[i] - mx); s += vals[i]; }
    red[ty][tx] = s;
    __syncthreads();
    if (ty == 0) {
        float s2 = 0.0f;
#pragma unroll
        for (int i = 0; i < 8; i++) s2 += red[i][tx];
        red[0][tx] = s2;
    }
    __syncthreads();
    float inv = 1.0f / red[0][tx];
#pragma unroll
    for (int i = 0; i < LC / 8; i++) {
        int l = ty + i * 8;
        outb[(size_t)l * LE] = __float2bfloat16_rn(vals[i] * inv);
    }
}

__global__ void alpha_kernel(const float* __restrict__ align_, __nv_bfloat16* __restrict__ alpha,
                             const int* __restrict__ emask)
{
    const int b = blockIdx.y, l = blockIdx.x, t = threadIdx.x;
    const float* row = align_ + ((size_t)b * LC + l) * LE;
    __nv_bfloat16* arow = alpha + ((size_t)b * LC + l) * LE;
    float v[4];
    float mx = -INFINITY;
#pragma unroll
    for (int j = 0; j < 4; j++) {
        int e = t + j * 256;
        v[j] = row[e] + (1.0f - (float)emask[b * LE + e]) * NEGV;
        mx = fmaxf(mx, v[j]);
    }
    __shared__ float sm[256];
    sm[t] = mx;
    __syncthreads();
    for (int s = 128; s > 0; s >>= 1) { if (t < s) sm[t] = fmaxf(sm[t], sm[t + s]); __syncthreads(); }
    mx = sm[0];
    __syncthreads();
    float sum = 0.0f;
#pragma unroll
    for (int j = 0; j < 4; j++) { v[j] = expf(v[j] - mx); sum += v[j]; }
    sm[t] = sum;
    __syncthreads();
    for (int s = 128; s > 0; s >>= 1) { if (t < s) sm[t] += sm[t + s]; __syncthreads(); }
    float inv = 1.0f / sm[0];
#pragma unroll
    for (int j = 0; j < 4; j++) arow[t + j * 256] = __float2bfloat16_rn(v[j] * inv);
}

__global__ void head_kernel(const float* __restrict__ r1, const float* __restrict__ r2,
                            const float* __restrict__ Wm, const float* __restrict__ bm,
                            const float* __restrict__ Wo, const float* __restrict__ bo,
                            float* __restrict__ out)
{
    const int b = blockIdx.x, t = threadIdx.x;
    __shared__ float mv[4 * DD];
    __shared__ float outacc[3];
    if (t < DD) {
        float a = r1[(size_t)b * DD + t], c = r2[(size_t)b * DD + t];
        mv[t] = a; mv[DD + t] = c; mv[2 * DD + t] = a * c; mv[3 * DD + t] = a - c;
    }
    if (t < 3) outacc[t] = 0.0f;
    __syncthreads();
    float acc = bm[t];
#pragma unroll 8
    for (int k = 0; k < 4 * DD; k++) acc = fmaf(mv[k], Wm[(size_t)k * MM + t], acc);
    float h = fmaxf(acc, 0.0f);
#pragma unroll
    for (int i = 0; i < 3; i++) atomicAdd(&outacc[i], h * Wo[(size_t)t * 3 + i]);
    __syncthreads();
    if (t < 3) out[(size_t)b * 3 + t] = outacc[t] + bo[t];
}

// ---------------- launch ----------------
extern "C" void kernel_launch(void* const* d_in, const int* in_sizes, int n_in,
                              void* d_out, int out_size)
{
    const float* criteria = (const float*)d_in[0];
    const float* ehr      = (const float*)d_in[1];
    const int*   cmask    = (const int*)d_in[2];
    const int*   emask    = (const int*)d_in[3];
    const float* Wa       = (const float*)d_in[4];
    const float* ba       = (const float*)d_in[5];
    const float* Wr       = (const float*)d_in[6];
    const float* br       = (const float*)d_in[7];
    const float* Wm       = (const float*)d_in[8];
    const float* bm       = (const float*)d_in[9];
    const float* Wo       = (const float*)d_in[10];
    const float* bo       = (const float*)d_in[11];
    float* out = (float*)d_out;

    float* base;
    cudaGetSymbolAddress((void**)&base, g_scratch);
    __nv_bfloat16* p_c     = (__nv_bfloat16*)(base + OFF_CB);
    __nv_bfloat16* p_e     = (__nv_bfloat16*)(base + OFF_EB);
    float*         p_align = base + OFF_ALIGN;
    __nv_bfloat16* p_beta  = (__nv_bfloat16*)(base + OFF_EB);     // alias: e dead after align
    __nv_bfloat16* p_alpha = (__nv_bfloat16*)(base + OFF_ALPHA);
    __nv_bfloat16* p_attc  = (__nv_bfloat16*)(base + OFF_CB);     // alias: c dead after align
    __nv_bfloat16* p_atte  = (__nv_bfloat16*)(base + OFF_ALPHA);  // alias: alpha dead after attc
    __nv_bfloat16* p_ehrB  = (__nv_bfloat16*)(base + OFF_EHRB);
    __nv_bfloat16* p_critB = (__nv_bfloat16*)(base + OFF_CRITB);
    __nv_bfloat16* p_WaB   = (__nv_bfloat16*)(base + OFF_WAB);
    __nv_bfloat16* p_WrB   = (__nv_bfloat16*)(base + OFF_WRB);
    float*         p_r1    = base + OFF_R1;
    float*         p_r2    = base + OFF_R2;

    // 0) one-time f32 -> bf16 conversions (bit-identical rounding to R12's in-loop pk)
    size_t nc = (size_t)BB * LC * DD, ne = (size_t)BB * LE * DD;
    convf2b<<<(int)(nc / 8 / 256), 256>>>(criteria, p_critB, nc);
    convf2b<<<(int)(ne / 8 / 256), 256>>>(ehr, p_ehrB, ne);
    convf2b<<<(DD * DD / 8 + 255) / 256, 256>>>(Wa, p_WaB, (size_t)DD * DD);
    convf2b<<<(2 * DD * DD / 8 + 255) / 256, 256>>>(Wr, p_WrB, (size_t)2 * DD * DD);
    // 1,2) projections (all-bf16 operands)
    mm_proj<<<dim3(DD / BN, (BB * LC) / BM), 256>>>(p_critB, p_WaB, ba, p_c, DD, DD);
    mm_proj<<<dim3(DD / BN, (BB * LE) / BM), 256>>>(p_ehrB, p_WaB, ba, p_e, DD, DD);
    // 3) align = c @ e^T -> f32
    mm_align<<<dim3(LE / BN, LC / BM, BB), 256>>>(
        p_c, p_e, p_align, LE, DD,
        (size_t)LC * DD, (size_t)LE * DD, (size_t)LC * LE);
    // 4,5) softmaxes
    beta_kernel<<<dim3(LE / 32, BB), dim3(32, 8)>>>(p_align, p_beta, cmask);
    alpha_kernel<<<dim3(LC, BB), 256>>>(p_align, p_alpha, emask);
    // 6) attc = alpha @ ehrB
    mm_attc<<<dim3(DD / BN, LC / BM, BB), 256>>>(
        p_alpha, p_ehrB, p_attc, DD, LE,
        (size_t)LC * LE, (size_t)LE * DD, (size_t)LC * DD);
    // 7) atte = beta^T @ critB (aliases alpha)
    mm_atte<<<dim3(DD / BN, LE / BM, BB), 256>>>(
        p_beta, p_critB, p_atte, DD, LC, LE,
        (size_t)LC * LE, (size_t)LC * DD, (size_t)LE * DD);
    // 8) r1, r2
    cudaMemsetAsync(p_r1, 0, (size_t)2 * BB * DD * sizeof(float));
    mm_concat_rs<<<dim3(DD / BN, LC / BM, BB), 256>>>(p_attc, p_critB, p_WrB, br, p_r1, LC);
    mm_concat_rs<<<dim3(DD / BN, LE / BM, BB), 256>>>(p_atte, p_ehrB, p_WrB, br, p_r2, LE);
    // 9) head
    head_kernel<<<BB, MM>>>(p_r1, p_r2, Wm, bm, Wo, bo, out);
}